// round 12
// baseline (speedup 1.0000x reference)
#include <cuda_runtime.h>
#include <cuda_bf16.h>
#include <math.h>
#include <stdint.h>

// GIN Grapher layer: enc+BN -> GINConv(scatter-add + MLP) -> FFN(2D) -> +x -> FFN(4D)
// GEMMs via bf16x3 emulated-fp32 on HMMA (mma.sync.m16n8k16).
// A operands pre-split (+BN/GELU) to bf16 hi/lo by asplit_kernel; GEMM mainloop is
// pure copy + MMA with double-buffered smem. BN stats fused into GEMM epilogue.

#define MAXN   50048
#define DIM    128
#define SM_ARR 4608            // shorts per smem array (128 rows x 36)
#define SM_BUF (4 * SM_ARR)    // shorts per stage buffer (AsH, AsL, BsH, BsL)
#define SMEM_BYTES (2 * SM_BUF * 2)   // 2 buffers, 2 bytes/short = 73728

// ---------------- scratch ----------------
__device__ float g_Z  [(size_t)MAXN * 512];
__device__ float g_T  [(size_t)MAXN * DIM];
__device__ float g_h0 [(size_t)MAXN * DIM];
__device__ float g_agg[(size_t)MAXN * DIM];
__device__ float g_h1 [(size_t)MAXN * DIM];
__device__ float g_h4 [(size_t)MAXN * DIM];
__device__ float g_colsum[512];
__device__ float g_colsqs[512];
__device__ float g_sc[512];                   // BN folded scale = gamma * rstd
__device__ float g_sh[512];                   // BN folded shift = beta - mean*scale
__device__ __nv_bfloat16 g_Wh[262144];        // weight splits, transposed [n][k]
__device__ __nv_bfloat16 g_Wl[262144];
__device__ __nv_bfloat16 g_Ah[(size_t)MAXN * 512];   // activation splits [m][k]
__device__ __nv_bfloat16 g_Al[(size_t)MAXN * 512];

__device__ __forceinline__ float gelu_exact(float v) {
    return 0.5f * v * (1.f + erff(v * 0.70710678118654752f));
}

__device__ __forceinline__ void mma_bf16(float* c, const unsigned* a, const unsigned* b) {
    asm volatile(
        "mma.sync.aligned.m16n8k16.row.col.f32.bf16.bf16.f32 "
        "{%0,%1,%2,%3}, {%4,%5,%6,%7}, {%8,%9}, {%0,%1,%2,%3};"
        : "+f"(c[0]), "+f"(c[1]), "+f"(c[2]), "+f"(c[3])
        : "r"(a[0]), "r"(a[1]), "r"(a[2]), "r"(a[3]), "r"(b[0]), "r"(b[1]));
}

// ---------------- weight split+transpose: W[K][Nc] -> Th/Tl[Nc][K] ----------------
__global__ void wsplit_kernel(const float* __restrict__ W,
                              __nv_bfloat16* __restrict__ Th,
                              __nv_bfloat16* __restrict__ Tl, int K, int Nc)
{
    int idx = blockIdx.x * 256 + threadIdx.x;
    if (idx >= K * Nc) return;
    int k = idx / Nc, n = idx - k * Nc;
    float w = W[idx];
    __nv_bfloat16 h = __float2bfloat16_rn(w);
    float rem = w - __bfloat162float(h);
    Th[(size_t)n * K + k] = h;
    Tl[(size_t)n * K + k] = __float2bfloat16_rn(rem);
}

// ---------------- activation split: X[M][Nc] fp32 -> Ah/Al bf16 (+BN/GELU) --------
// mode 0: plain; 1: BN affine; 2: BN affine + exact GELU
__global__ void asplit_kernel(const float* __restrict__ X,
                              __nv_bfloat16* __restrict__ Ah,
                              __nv_bfloat16* __restrict__ Al,
                              int total, int Nc, int mode)
{
    int idx = (blockIdx.x * 256 + threadIdx.x) * 4;
    if (idx >= total) return;
    int c = idx % Nc;
    float4 xv = *(const float4*)(X + idx);
    float v[4] = {xv.x, xv.y, xv.z, xv.w};
    unsigned short hb[4], lb[4];
    #pragma unroll
    for (int j = 0; j < 4; j++) {
        float w = v[j];
        if (mode >= 1) w = fmaf(g_sc[c + j], w, g_sh[c + j]);
        if (mode == 2) w = gelu_exact(w);
        __nv_bfloat16 h = __float2bfloat16_rn(w);
        hb[j] = __bfloat16_as_ushort(h);
        lb[j] = __bfloat16_as_ushort(__float2bfloat16_rn(w - __bfloat162float(h)));
    }
    uint2 hp = make_uint2((unsigned)hb[0] | ((unsigned)hb[1] << 16),
                          (unsigned)hb[2] | ((unsigned)hb[3] << 16));
    uint2 lp = make_uint2((unsigned)lb[0] | ((unsigned)lb[1] << 16),
                          (unsigned)lb[2] | ((unsigned)lb[3] << 16));
    *(uint2*)(Ah + idx) = hp;
    *(uint2*)(Al + idx) = lp;
}

// ---------------- bf16x3 GEMM, double-buffered ----------------
// C[M,Nc] = A[M,K] @ W[K,Nc] + bias;  A given as hi/lo bf16 [M][K] (pre-split),
// W as transposed hi/lo bf16 [Nc][K]. statsOut: column sum/sumsq into g_colsum/sqs.
// CTA 128x128, BK=32, 256 threads (8 warps: 2M x 4N), warp tile 64x32.
__global__ __launch_bounds__(256)
void gemm_bf16x3_kernel(const __nv_bfloat16* __restrict__ Ahi,
                        const __nv_bfloat16* __restrict__ Alo,
                        const __nv_bfloat16* __restrict__ Bhi,
                        const __nv_bfloat16* __restrict__ Blo,
                        const float* __restrict__ bias, float* __restrict__ C,
                        int M, int K, int Nc, int statsOut)
{
    extern __shared__ unsigned short sm[];

    const int tid   = threadIdx.x;
    const int lane  = tid & 31, wid = tid >> 5;
    const int g     = lane >> 2, t4 = lane & 3;
    const int warpM = wid & 1,  warpN = wid >> 1;
    const int row0  = blockIdx.y * 128, col0 = blockIdx.x * 128;

    const int ldRow = tid >> 1;          // 0..127
    const int ldK   = (tid & 1) * 16;    // 0 or 16

    const __nv_bfloat16* AhP = Ahi + (size_t)(row0 + ldRow) * K + ldK;
    const __nv_bfloat16* AlP = Alo + (size_t)(row0 + ldRow) * K + ldK;
    const __nv_bfloat16* BhP = Bhi + (size_t)(col0 + ldRow) * K + ldK;
    const __nv_bfloat16* BlP = Blo + (size_t)(col0 + ldRow) * K + ldK;

    float acc[4][4][4];
    #pragma unroll
    for (int mi = 0; mi < 4; mi++)
        #pragma unroll
        for (int ni = 0; ni < 4; ni++)
            #pragma unroll
            for (int j = 0; j < 4; j++) acc[mi][ni][j] = 0.f;

    uint4 p[8];
    auto loadTile = [&](int k) {
        p[0] = *(const uint4*)(AhP + k);  p[1] = *(const uint4*)(AhP + k + 8);
        p[2] = *(const uint4*)(AlP + k);  p[3] = *(const uint4*)(AlP + k + 8);
        p[4] = *(const uint4*)(BhP + k);  p[5] = *(const uint4*)(BhP + k + 8);
        p[6] = *(const uint4*)(BlP + k);  p[7] = *(const uint4*)(BlP + k + 8);
    };
    auto storeTile = [&](int b) {
        unsigned short* base = sm + b * SM_BUF + ldRow * 36 + ldK;
        #pragma unroll
        for (int arr = 0; arr < 4; arr++) {
            uint4 v0 = p[arr * 2], v1 = p[arr * 2 + 1];
            unsigned short* q = base + arr * SM_ARR;
            *(uint2*)(q + 0)  = make_uint2(v0.x, v0.y);
            *(uint2*)(q + 4)  = make_uint2(v0.z, v0.w);
            *(uint2*)(q + 8)  = make_uint2(v1.x, v1.y);
            *(uint2*)(q + 12) = make_uint2(v1.z, v1.w);
        }
    };

    const int nIter = K >> 5;
    loadTile(0);
    storeTile(0);
    __syncthreads();
    int cur = 0;

    for (int i = 0; i < nIter; i++) {
        bool hasNext = (i + 1) < nIter;
        if (hasNext) loadTile((i + 1) * 32);

        const unsigned short* As_H = sm + cur * SM_BUF + 0 * SM_ARR;
        const unsigned short* As_L = sm + cur * SM_BUF + 1 * SM_ARR;
        const unsigned short* Bs_H = sm + cur * SM_BUF + 2 * SM_ARR;
        const unsigned short* Bs_L = sm + cur * SM_BUF + 3 * SM_ARR;

        #pragma unroll
        for (int s = 0; s < 2; s++) {
            const int ks = s * 16;
            unsigned bH[4][2], bL[4][2];
            #pragma unroll
            for (int ni = 0; ni < 4; ni++) {
                int n = warpN * 32 + ni * 8 + g;
                bH[ni][0] = *(const unsigned*)&Bs_H[n * 36 + ks + t4 * 2];
                bH[ni][1] = *(const unsigned*)&Bs_H[n * 36 + ks + t4 * 2 + 8];
                bL[ni][0] = *(const unsigned*)&Bs_L[n * 36 + ks + t4 * 2];
                bL[ni][1] = *(const unsigned*)&Bs_L[n * 36 + ks + t4 * 2 + 8];
            }
            #pragma unroll
            for (int mi = 0; mi < 4; mi++) {
                int m = warpM * 64 + mi * 16 + g;
                unsigned aH[4], aL[4];
                aH[0] = *(const unsigned*)&As_H[m * 36 + ks + t4 * 2];
                aH[1] = *(const unsigned*)&As_H[(m + 8) * 36 + ks + t4 * 2];
                aH[2] = *(const unsigned*)&As_H[m * 36 + ks + t4 * 2 + 8];
                aH[3] = *(const unsigned*)&As_H[(m + 8) * 36 + ks + t4 * 2 + 8];
                aL[0] = *(const unsigned*)&As_L[m * 36 + ks + t4 * 2];
                aL[1] = *(const unsigned*)&As_L[(m + 8) * 36 + ks + t4 * 2];
                aL[2] = *(const unsigned*)&As_L[m * 36 + ks + t4 * 2 + 8];
                aL[3] = *(const unsigned*)&As_L[(m + 8) * 36 + ks + t4 * 2 + 8];
                #pragma unroll
                for (int ni = 0; ni < 4; ni++) {
                    mma_bf16(acc[mi][ni], aH, bH[ni]);
                    mma_bf16(acc[mi][ni], aH, bL[ni]);
                    mma_bf16(acc[mi][ni], aL, bH[ni]);
                }
            }
        }

        if (hasNext) {
            __syncthreads();          // all warps done reading buf cur^1 (iter i-1)
            storeTile(cur ^ 1);
            __syncthreads();          // stores visible before next compute
            cur ^= 1;
        }
    }

    // ---- epilogue: bias, store, fused column stats ----
    float bv[4][2];
    #pragma unroll
    for (int ni = 0; ni < 4; ni++) {
        float2 b2 = *(const float2*)(bias + col0 + warpN * 32 + ni * 8 + t4 * 2);
        bv[ni][0] = b2.x; bv[ni][1] = b2.y;
    }
    float sP[4][2], qP[4][2];
    #pragma unroll
    for (int ni = 0; ni < 4; ni++)
        #pragma unroll
        for (int j = 0; j < 2; j++) { sP[ni][j] = 0.f; qP[ni][j] = 0.f; }

    #pragma unroll
    for (int mi = 0; mi < 4; mi++) {
        int r0 = row0 + warpM * 64 + mi * 16 + g;
        int r1 = r0 + 8;
        bool v0 = r0 < M, v1 = r1 < M;
        #pragma unroll
        for (int ni = 0; ni < 4; ni++) {
            int c = col0 + warpN * 32 + ni * 8 + t4 * 2;
            float o0 = acc[mi][ni][0] + bv[ni][0];
            float o1 = acc[mi][ni][1] + bv[ni][1];
            float o2 = acc[mi][ni][2] + bv[ni][0];
            float o3 = acc[mi][ni][3] + bv[ni][1];
            if (v0) {
                *(float2*)(C + (size_t)r0 * Nc + c) = make_float2(o0, o1);
                sP[ni][0] += o0; qP[ni][0] += o0 * o0;
                sP[ni][1] += o1; qP[ni][1] += o1 * o1;
            }
            if (v1) {
                *(float2*)(C + (size_t)r1 * Nc + c) = make_float2(o2, o3);
                sP[ni][0] += o2; qP[ni][0] += o2 * o2;
                sP[ni][1] += o3; qP[ni][1] += o3 * o3;
            }
        }
    }
    if (statsOut) {
        #pragma unroll
        for (int off = 16; off >= 4; off >>= 1) {
            #pragma unroll
            for (int ni = 0; ni < 4; ni++)
                #pragma unroll
                for (int j = 0; j < 2; j++) {
                    sP[ni][j] += __shfl_down_sync(0xffffffffu, sP[ni][j], off);
                    qP[ni][j] += __shfl_down_sync(0xffffffffu, qP[ni][j], off);
                }
        }
        if (lane < 4) {
            #pragma unroll
            for (int ni = 0; ni < 4; ni++)
                #pragma unroll
                for (int j = 0; j < 2; j++) {
                    int c = col0 + warpN * 32 + ni * 8 + lane * 2 + j;
                    atomicAdd(&g_colsum[c], sP[ni][j]);
                    atomicAdd(&g_colsqs[c], qP[ni][j]);
                }
        }
    }
}

// ---------------- finalize: fold BN params, re-zero accumulators ----------------
__global__ void bn_finalize_kernel(int M, int Nc,
                                   const float* __restrict__ gamma,
                                   const float* __restrict__ beta)
{
    int c = threadIdx.x;
    if (c < Nc) {
        float s = g_colsum[c], q = g_colsqs[c];
        float m = s / (float)M;
        float v = q / (float)M - m * m;
        float rs = rsqrtf(v + 1e-5f);
        float sc = gamma[c] * rs;
        g_sc[c] = sc;
        g_sh[c] = beta[c] - m * sc;
    }
    g_colsum[c] = 0.f;
    g_colsqs[c] = 0.f;
}

// ---------------- standalone BN apply (+ residuals, dual output) ----------------
__global__ void bn_apply_kernel(const float* __restrict__ Z,
                                const float* __restrict__ r1,
                                const float* __restrict__ r2,
                                float* __restrict__ out,
                                float* __restrict__ out2,
                                int M, int Nc)
{
    size_t idx = ((size_t)blockIdx.x * blockDim.x + threadIdx.x) * 4;
    if (idx >= (size_t)M * Nc) return;
    int c = (int)(idx % (size_t)Nc);

    float4 z = *(const float4*)(Z + idx);
    float o[4] = {
        fmaf(g_sc[c + 0], z.x, g_sh[c + 0]),
        fmaf(g_sc[c + 1], z.y, g_sh[c + 1]),
        fmaf(g_sc[c + 2], z.z, g_sh[c + 2]),
        fmaf(g_sc[c + 3], z.w, g_sh[c + 3])
    };
    if (r1) {
        float4 a = *(const float4*)(r1 + idx);
        o[0] += a.x; o[1] += a.y; o[2] += a.z; o[3] += a.w;
    }
    if (r2) {
        float4 a = *(const float4*)(r2 + idx);
        o[0] += a.x; o[1] += a.y; o[2] += a.z; o[3] += a.w;
    }
    float4 ov = make_float4(o[0], o[1], o[2], o[3]);
    *(float4*)(out + idx) = ov;
    if (out2) *(float4*)(out2 + idx) = ov;
}

// ---------------- edge scatter-add: agg[dst] += h0[src] ----------------
__global__ void scatter_add_kernel(const float* __restrict__ H,
                                   const int* __restrict__ src,
                                   const int* __restrict__ dst,
                                   float* __restrict__ agg, int E)
{
    int e = blockIdx.x * 8 + threadIdx.y;
    if (e >= E) return;
    int s = src[e], d = dst[e];
    const float* hs = H + (size_t)s * DIM;
    float* ad = agg + (size_t)d * DIM;
    int l = threadIdx.x;
    #pragma unroll
    for (int j = 0; j < 4; j++) {
        atomicAdd(ad + l + j * 32, __ldg(hs + l + j * 32));
    }
}

// ---------------- host orchestration ----------------
extern "C" void kernel_launch(void* const* d_in, const int* in_sizes, int n_in,
                              void* d_out, int out_size)
{
    const float* x     = (const float*)d_in[0];
    const int*   ei    = (const int*)  d_in[1];
    const float* encW  = (const float*)d_in[2];
    const float* encb  = (const float*)d_in[3];
    const float* bng   = (const float*)d_in[4];
    const float* bnb   = (const float*)d_in[5];
    const float* gW1   = (const float*)d_in[6];
    const float* gb1   = (const float*)d_in[7];
    const float* gg    = (const float*)d_in[8];
    const float* gbb   = (const float*)d_in[9];
    const float* gW2   = (const float*)d_in[10];
    const float* gb2   = (const float*)d_in[11];
    const float* f2W1  = (const float*)d_in[12];
    const float* f2b1  = (const float*)d_in[13];
    const float* f2g1  = (const float*)d_in[14];
    const float* f2bb1 = (const float*)d_in[15];
    const float* f2W2  = (const float*)d_in[16];
    const float* f2b2  = (const float*)d_in[17];
    const float* f2g2  = (const float*)d_in[18];
    const float* f2bb2 = (const float*)d_in[19];
    const float* fnW1  = (const float*)d_in[20];
    const float* fnb1  = (const float*)d_in[21];
    const float* fng1  = (const float*)d_in[22];
    const float* fnbb1 = (const float*)d_in[23];
    const float* fnW2  = (const float*)d_in[24];
    const float* fnb2  = (const float*)d_in[25];
    const float* fng2  = (const float*)d_in[26];
    const float* fnbb2 = (const float*)d_in[27];

    const int M = in_sizes[0] / DIM;
    const int E = in_sizes[1] / 2;

    float *Z, *T, *h0, *agg, *h1, *h4;
    __nv_bfloat16 *Wh, *Wl, *Ah, *Al;
    cudaGetSymbolAddress((void**)&Z,   g_Z);
    cudaGetSymbolAddress((void**)&T,   g_T);
    cudaGetSymbolAddress((void**)&h0,  g_h0);
    cudaGetSymbolAddress((void**)&agg, g_agg);
    cudaGetSymbolAddress((void**)&h1,  g_h1);
    cudaGetSymbolAddress((void**)&h4,  g_h4);
    cudaGetSymbolAddress((void**)&Wh,  g_Wh);
    cudaGetSymbolAddress((void**)&Wl,  g_Wl);
    cudaGetSymbolAddress((void**)&Ah,  g_Ah);
    cudaGetSymbolAddress((void**)&Al,  g_Al);

    cudaFuncSetAttribute(gemm_bf16x3_kernel,
                         cudaFuncAttributeMaxDynamicSharedMemorySize, SMEM_BYTES);

    // weight scratch offsets (elements)
    const size_t oEnc = 0, oG1 = 16384, oG2 = 32768, oF21 = 49152,
                 oF22 = 81920, oFN1 = 114688, oFN2 = 180224;

    auto wsplit = [&](const float* W, size_t off, int K, int Nc) {
        int tot = K * Nc;
        wsplit_kernel<<<(tot + 255) / 256, 256>>>(W, Wh + off, Wl + off, K, Nc);
    };
    auto asplit = [&](const float* X, int Nc, int mode) {
        int tot = M * Nc;
        asplit_kernel<<<(tot / 4 + 255) / 256, 256>>>(X, Ah, Al, tot, Nc, mode);
    };
    const int gy = (M + 127) / 128;
    auto gemm = [&](size_t woff, const float* b, float* C, int K, int Nc, int statsOut) {
        dim3 grid(Nc / 128, gy);
        gemm_bf16x3_kernel<<<grid, 256, SMEM_BYTES>>>(Ah, Al, Wh + woff, Wl + woff,
                                                      b, C, M, K, Nc, statsOut);
    };
    auto finalize = [&](int Nc, const float* ga, const float* be) {
        bn_finalize_kernel<<<1, 512>>>(M, Nc, ga, be);
    };
    auto bn = [&](const float* Zp, const float* r1, const float* r2,
                  float* o, float* o2, int Nc) {
        size_t tot = (size_t)M * Nc / 4;
        bn_apply_kernel<<<(unsigned)((tot + 255) / 256), 256>>>(Zp, r1, r2, o, o2, M, Nc);
    };

    // 0) weight splits + zero stats accumulators
    wsplit(encW, oEnc, DIM, DIM);
    wsplit(gW1,  oG1,  DIM, DIM);
    wsplit(gW2,  oG2,  DIM, DIM);
    wsplit(f2W1, oF21, DIM, 2 * DIM);
    wsplit(f2W2, oF22, 2 * DIM, DIM);
    wsplit(fnW1, oFN1, DIM, 4 * DIM);
    wsplit(fnW2, oFN2, 4 * DIM, DIM);
    finalize(0, encb, encb);

    // 1) Z = x @ encW + encb (stats) -> h0 = BN(Z), agg = h0
    asplit(x, DIM, 0);
    gemm(oEnc, encb, Z, DIM, DIM, 1);
    finalize(DIM, bng, bnb);
    bn(Z, nullptr, nullptr, h0, agg, DIM);

    // 2) agg[dst] += h0[src]
    {
        dim3 blk(32, 8);
        scatter_add_kernel<<<(E + 7) / 8, blk>>>(h0, ei, ei + E, agg, E);
    }

    // 3) GIN MLP: Z = agg @ gW1 (stats); h1 = gelu(BN(Z)) @ gW2
    asplit(agg, DIM, 0);
    gemm(oG1, gb1, Z, DIM, DIM, 1);
    finalize(DIM, gg, gbb);
    asplit(Z, DIM, 2);
    gemm(oG2, gb2, h1, DIM, DIM, 0);

    // 4) fc2 FFN + residuals
    asplit(h1, DIM, 0);
    gemm(oF21, f2b1, Z, DIM, 2 * DIM, 1);
    finalize(2 * DIM, f2g1, f2bb1);
    asplit(Z, 2 * DIM, 2);
    gemm(oF22, f2b2, T, 2 * DIM, DIM, 1);
    finalize(DIM, f2g2, f2bb2);
    bn(T, h1, x, h4, nullptr, DIM);           // h4 = BN(T) + h1 + x

    // 5) final FFN
    asplit(h4, DIM, 0);
    gemm(oFN1, fnb1, Z, DIM, 4 * DIM, 1);
    finalize(4 * DIM, fng1, fnbb1);
    asplit(Z, 4 * DIM, 2);
    gemm(oFN2, fnb2, T, 4 * DIM, DIM, 1);
    finalize(DIM, fng2, fnbb2);
    bn(T, h4, nullptr, (float*)d_out, nullptr, DIM);  // out = BN(T) + h4
}